// round 6
// baseline (speedup 1.0000x reference)
#include <cuda_runtime.h>
#include <cuda_bf16.h>

#define IMG_R 384
#define IMG_C 384
#define N_COLS 768
#define N_VIEWS 256
#define DSPACE_F 1.5f
#define NSPLIT 8
#define ROWS_PER_SPLIT (IMG_R / NSPLIT)   // 48

__global__ __launch_bounds__(256)
void fanbeam_gather_kernel(
    const float* __restrict__ img,      // (R, C)
    const float* __restrict__ src_a,    // (V, 1, 2)
    const float* __restrict__ detc_a,   // (V, 1, 2)
    const float* __restrict__ u_a,      // (V, 1, 2)
    const float* __restrict__ center_a, // (2,)
    const float* __restrict__ cdir_a,   // (2,)
    float* __restrict__ out)            // (V, N_COLS)
{
    const int v       = blockIdx.y;
    const int j_local = threadIdx.x & 31;
    const int split   = threadIdx.x >> 5;            // 0..7 (= warp id)
    const int j       = (blockIdx.x << 5) | j_local; // detector column

    // ---- per-view geometry ----
    const float sx  = src_a[2 * v],  sy  = src_a[2 * v + 1];
    const float dcx = detc_a[2 * v], dcy = detc_a[2 * v + 1];
    const float ux  = u_a[2 * v],    uy  = u_a[2 * v + 1];
    const float cx  = center_a[0],   cy  = center_a[1];
    const float cdx = cdir_a[0],     cdy = cdir_a[1];

    const float rdx = -cdy, rdy = cdx;
    const float vzx = cx - 0.5f * (IMG_R - 1) * rdx - 0.5f * (IMG_C - 1) * cdx;
    const float vzy = cy - 0.5f * (IMG_R - 1) * rdy - 0.5f * (IMG_C - 1) * cdy;

    const float nx = -uy, ny = ux;
    const float ref_d = dcx * nx + dcy * ny;
    const float src_d = sx * nx + sy * ny;
    const float nu    = ref_d - src_d;                      // t numerator, >0 here
    const float src_u = sx * ux + sy * uy;
    const float uu    = ux * ux + uy * uy;
    const float zero_u = (dcx * ux + dcy * uy) - 0.5f * (N_COLS - 1) * DSPACE_F * uu;
    const float invD  = 1.0f / DSPACE_F;
    const float su0D  = (src_u - zero_u) * invD;            // pre-scaled by 1/DSPACE

    const float dn00  = vzx * nx + vzy * ny - src_d;
    const float dnr   = rdx * nx + rdy * ny;
    const float dnc   = cdx * nx + cdy * ny;
    const float pu00D = (vzx * ux + vzy * uy - src_u) * invD;
    const float purD  = (rdx * ux + rdy * uy) * invD;
    const float pucD  = (cdx * ux + cdy * uy) * invD;

    // col(r,c)*den(r,c) = A(r) + B*c ;  den(r,c) = dn0(r) + c*dnc > 0
    const float A0 = su0D * dn00 + nu * pu00D;
    const float Ar = su0D * dnr  + nu * purD;
    const float Bc = su0D * dnc  + nu * pucD;

    // window constraints:  col > j-1 and col < j+1 as linear half-planes
    const float jf = (float)j;
    const float jm = jf - 1.0f, jp = jf + 1.0f;
    const float bm = Bc - jm * dnc;
    const float bp = Bc - jp * dnc;
    const float rBm = __frcp_rn(bm);
    const float rBp = __frcp_rn(bp);
    const bool  m_lower = (bm > 0.0f);
    const bool  p_lower = (bp < 0.0f);

    // analytic row range (superset; per-row check remains as safety net)
    const float am0 = A0 - jm * dn00, amr = Ar - jm * dnr;
    const float ap0 = A0 - jp * dn00, apr = Ar - jp * dnr;
    const float Km  = fmaxf(0.0f, bm * (float)(IMG_C - 1));
    const float Kp  = fminf(0.0f, bp * (float)(IMG_C - 1));
    float rlo_f = 0.0f, rhi_f = (float)(IMG_R - 1);
    bool empty = false;
    {
        const float s = am0 + Km;
        if (amr > 0.0f)       rlo_f = fmaxf(rlo_f, __fdividef(-s, amr));
        else if (amr < 0.0f)  rhi_f = fminf(rhi_f, __fdividef(-s, amr));
        else if (!(s > 0.0f)) empty = true;
    }
    {
        const float s = ap0 + Kp;
        if (apr < 0.0f)       rlo_f = fmaxf(rlo_f, __fdividef(-s, apr));
        else if (apr > 0.0f)  rhi_f = fminf(rhi_f, __fdividef(-s, apr));
        else if (!(s < 0.0f)) empty = true;
    }
    int r0 = 1, r1 = 0;
    if (!empty && rhi_f >= rlo_f) {
        r0 = max(split * ROWS_PER_SPLIT,                      (int)floorf(rlo_f) - 1);
        r1 = min(split * ROWS_PER_SPLIT + ROWS_PER_SPLIT - 1, (int)ceilf(rhi_f) + 1);
    }

    float acc = 0.0f;
    const float* rowBase = img + r0 * IMG_C;
    float rf = (float)r0;

    for (int r = r0; r <= r1; ++r, rowBase += IMG_C, rf += 1.0f) {
        const float dn0 = fmaf(rf, dnr, dn00);
        const float AD  = fmaf(rf, Ar,  A0);

        const float cm = fmaf(jm, dn0, -AD) * rBm;   // c-bound from col>j-1
        const float cp = fmaf(jp, dn0, -AD) * rBp;   // c-bound from col<j+1
        float lo = 0.0f, hi = (float)(IMG_C - 1);
        if (m_lower) lo = fmaxf(lo, cm); else hi = fminf(hi, cm);
        if (p_lower) lo = fmaxf(lo, cp); else hi = fminf(hi, cp);
        if (hi < lo) continue;

        const int ilo = max(0, (int)ceilf(lo - 0.02f));
        const int ihi = min(IMG_C - 1, (int)floorf(hi + 0.02f));
        if (ihi < ilo) continue;

        const float cf0 = (float)ilo;
        float den = fmaf(cf0, dnc,  dn0);
        float puD = fmaf(cf0, pucD, fmaf(rf, purD, pu00D));

        for (int c = ilo; c <= ihi; ++c) {
            const float t   = __fdividef(nu, den);
            const float col = fmaf(t, puD, su0D);
            const float w   = 1.0f - fabsf(col - jf);
            if (w > 0.0f)
                acc = fmaf(w, rowBase[c], acc);
            den += dnc;
            puD += pucD;
        }
    }

    // in-block reduction over the 8 row-splits
    __shared__ float red[NSPLIT][32];
    red[split][j_local] = acc;
    __syncthreads();
    if (split == 0) {
        float s = red[0][j_local];
        #pragma unroll
        for (int k = 1; k < NSPLIT; ++k)
            s += red[k][j_local];
        out[v * N_COLS + j] = s;
    }
}

extern "C" void kernel_launch(void* const* d_in, const int* in_sizes, int n_in,
                              void* d_out, int out_size) {
    const float* img    = (const float*)d_in[0];
    const float* src    = (const float*)d_in[1];
    const float* detc   = (const float*)d_in[2];
    const float* u      = (const float*)d_in[3];
    const float* center = (const float*)d_in[4];
    const float* cdir   = (const float*)d_in[5];
    float* out = (float*)d_out;

    dim3 grid(N_COLS / 32, N_VIEWS);
    fanbeam_gather_kernel<<<grid, 256>>>(img, src, detc, u, center, cdir, out);
}

// round 11
// speedup vs baseline: 1.8531x; 1.8531x over previous
#include <cuda_runtime.h>
#include <cuda_bf16.h>

#define IMG_R 384
#define IMG_C 384
#define NPIX (IMG_R * IMG_C)
#define N_COLS 768
#define N_VIEWS 256
#define DSPACE_F 1.5f
#define NSPLIT 8

__global__ __launch_bounds__(256)
void fanbeam_gather_kernel(
    const float* __restrict__ img,      // (R, C)
    const float* __restrict__ src_a,    // (V, 1, 2)
    const float* __restrict__ detc_a,   // (V, 1, 2)
    const float* __restrict__ u_a,      // (V, 1, 2)
    const float* __restrict__ center_a, // (2,)
    const float* __restrict__ cdir_a,   // (2,)
    float* __restrict__ out)            // (V, N_COLS)
{
    const int v     = blockIdx.y;
    const int lane  = threadIdx.x & 31;
    const int split = threadIdx.x >> 5;              // 0..7, strided rows
    const int j     = (blockIdx.x << 5) | lane;      // detector column

    // ---- per-view geometry (validated in R3) ----
    const float sx  = src_a[2 * v],  sy  = src_a[2 * v + 1];
    const float dcx = detc_a[2 * v], dcy = detc_a[2 * v + 1];
    const float ux  = u_a[2 * v],    uy  = u_a[2 * v + 1];
    const float cx  = center_a[0],   cy  = center_a[1];
    const float cdx = cdir_a[0],     cdy = cdir_a[1];

    const float rdx = -cdy, rdy = cdx;
    const float vzx = cx - 0.5f * (IMG_R - 1) * rdx - 0.5f * (IMG_C - 1) * cdx;
    const float vzy = cy - 0.5f * (IMG_R - 1) * rdy - 0.5f * (IMG_C - 1) * cdy;

    const float nx = -uy, ny = ux;
    const float ref_d = dcx * nx + dcy * ny;
    const float src_d = sx * nx + sy * ny;
    const float nu    = ref_d - src_d;               // t numerator, >0 in this geometry
    const float src_u = sx * ux + sy * uy;
    const float uu    = ux * ux + uy * uy;
    const float zero_u = (dcx * ux + dcy * uy) - 0.5f * (N_COLS - 1) * DSPACE_F * uu;
    const float invD  = 1.0f / DSPACE_F;
    const float su0D  = (src_u - zero_u) * invD;

    const float dn00  = vzx * nx + vzy * ny - src_d;
    const float dnr   = rdx * nx + rdy * ny;
    const float dnc   = cdx * nx + cdy * ny;
    const float pu00D = (vzx * ux + vzy * uy - src_u) * invD;
    const float purD  = (rdx * ux + rdy * uy) * invD;
    const float pucD  = (cdx * ux + cdy * uy) * invD;

    // col(r,c)*den(r,c) = A(r) + B*c ; den(r,c) = dn0(r) + c*dnc > 0
    const float A0 = su0D * dn00 + nu * pu00D;
    const float Ar = su0D * dnr  + nu * purD;
    const float Bc = su0D * dnc  + nu * pucD;

    const float jf   = (float)j;
    const float jm   = jf - 1.0f, jp = jf + 1.0f;
    const float sujD = su0D - jf;

    // ---- window bounds as linear functions of r ----
    // m: col > j-1  <=>  c*bm > jm*dn0(r) - A(r) ; p: col < j+1 <=> c*bp < jp*dn0(r) - A(r)
    const float bm = Bc - jm * dnc;
    const float bp = Bc - jp * dnc;
    const float rBm = __frcp_rn(bm);
    const float rBp = __frcp_rn(bp);
    const float Lm0 = (jm * dn00 - A0) * rBm, Lmr = (jm * dnr - Ar) * rBm;
    const float Lp0 = (jp * dn00 - A0) * rBp, Lpr = (jp * dnr - Ar) * rBp;
    const bool m_act = fabsf(bm) > 1e-30f;
    const bool p_act = fabsf(bp) > 1e-30f;

    // assign each constraint as a lower- or upper-bound line (margin 0.02 folded in)
    const bool mlow = m_act && (bm > 0.0f);
    const bool mup  = m_act && (bm < 0.0f);
    const bool plow = p_act && (bp < 0.0f);
    const bool pup  = p_act && (bp > 0.0f);
    float lo1b = mlow ? Lm0 - 0.02f : -1e30f,  lo1s = mlow ? Lmr : 0.0f;
    float hi1b = mup  ? Lm0 + 0.02f :  1e30f,  hi1s = mup  ? Lmr : 0.0f;
    float lo2b = plow ? Lp0 - 0.02f : -1e30f,  lo2s = plow ? Lpr : 0.0f;
    float hi2b = pup  ? Lp0 + 0.02f :  1e30f,  hi2s = pup  ? Lpr : 0.0f;

    // ---- analytic row range (superset; validated in R3) ----
    const float am0 = A0 - jm * dn00, amr = Ar - jm * dnr;
    const float ap0 = A0 - jp * dn00, apr = Ar - jp * dnr;
    const float Km  = fmaxf(0.0f, bm * (float)(IMG_C - 1));
    const float Kp  = fminf(0.0f, bp * (float)(IMG_C - 1));
    float rlo_f = 0.0f, rhi_f = (float)(IMG_R - 1);
    bool empty = false;
    {
        const float s = am0 + Km;
        if (amr > 0.0f)       rlo_f = fmaxf(rlo_f, __fdividef(-s, amr));
        else if (amr < 0.0f)  rhi_f = fminf(rhi_f, __fdividef(-s, amr));
        else if (!(s > 0.0f)) empty = true;
    }
    {
        const float s = ap0 + Kp;
        if (apr < 0.0f)       rlo_f = fmaxf(rlo_f, __fdividef(-s, apr));
        else if (apr > 0.0f)  rhi_f = fminf(rhi_f, __fdividef(-s, apr));
        else if (!(s < 0.0f)) empty = true;
    }
    int r0 = 0, r1 = -1;
    if (!empty && rhi_f >= rlo_f) {
        r0 = max(0, (int)floorf(rlo_f) - 1);
        r1 = min(IMG_R - 1, (int)ceilf(rhi_f) + 1);
    }

    // strided rows: this thread handles r = r0s, r0s+8, ...
    const int r0s   = r0 + ((split - r0) & (NSPLIT - 1));
    int nrows       = (r1 >= r0s) ? ((r1 - r0s) >> 3) + 1 : 0;
    const int nrows_w = __reduce_max_sync(0xffffffffu, nrows);

    // per-lane line state at r = r0s
    const float rs = (float)r0s;
    float lo1 = fmaf(rs, lo1s, lo1b), lo2 = fmaf(rs, lo2s, lo2b);
    float hi1 = fmaf(rs, hi1s, hi1b), hi2 = fmaf(rs, hi2s, hi2b);
    const float lo1st = 8.0f * lo1s, lo2st = 8.0f * lo2s;
    const float hi1st = 8.0f * hi1s, hi2st = 8.0f * hi2s;
    float dn0v = fmaf(rs, dnr,  dn00);
    float pu0v = fmaf(rs, purD, pu00D);
    const float dnr8 = 8.0f * dnr, pur8 = 8.0f * purD;
    int offr = r0s * IMG_C;

    float acc = 0.0f;

    for (int k = 0; k < nrows_w; ++k) {
        const float lo = fmaxf(fmaxf(lo1, lo2), 0.0f);
        const float hi = fminf(fminf(hi1, hi2), (float)(IMG_C - 1));
        const float cf = ceilf(lo);
        const int   n  = (int)(floorf(hi) - cf);      // trips-1 for this lane (may be <0)
        const bool  pr = (k < nrows);                 // row-valid for this lane
        const int   nw = __reduce_max_sync(0xffffffffu, pr ? n : -1);

        if (nw >= 0) {
            float den = fmaf(cf, dnc,  dn0v);
            float puD = fmaf(cf, pucD, pu0v);
            int   off = offr + (int)fminf(cf, (float)IMG_C);
            for (int kk = 0; kk <= nw; ++kk) {
                const float t  = __fdividef(nu, den);
                float w = 1.0f - fabsf(fmaf(t, puD, sujD));
                w = fmaxf(w, 0.0f);
                w = (pr && kk <= n) ? w : 0.0f;       // branchless lane mask
                const int offc = min(off, NPIX - 1);  // safe address (masked anyway)
                acc = fmaf(w, img[offc], acc);
                den += dnc; puD += pucD; ++off;
            }
        }
        lo1 += lo1st; lo2 += lo2st; hi1 += hi1st; hi2 += hi2st;
        dn0v += dnr8; pu0v += pur8; offr += NSPLIT * IMG_C;
    }

    // in-block reduction over the 8 strided splits (equal work -> cheap barrier)
    __shared__ float red[NSPLIT][32];
    red[split][lane] = acc;
    __syncthreads();
    if (split == 0) {
        float s = red[0][lane];
        #pragma unroll
        for (int kk = 1; kk < NSPLIT; ++kk)
            s += red[kk][lane];
        out[v * N_COLS + j] = s;
    }
}

extern "C" void kernel_launch(void* const* d_in, const int* in_sizes, int n_in,
                              void* d_out, int out_size) {
    const float* img    = (const float*)d_in[0];
    const float* src    = (const float*)d_in[1];
    const float* detc   = (const float*)d_in[2];
    const float* u      = (const float*)d_in[3];
    const float* center = (const float*)d_in[4];
    const float* cdir   = (const float*)d_in[5];
    float* out = (float*)d_out;

    dim3 grid(N_COLS / 32, N_VIEWS);
    fanbeam_gather_kernel<<<grid, 256>>>(img, src, detc, u, center, cdir, out);
}

// round 16
// speedup vs baseline: 2.0451x; 1.1036x over previous
#include <cuda_runtime.h>
#include <cuda_bf16.h>

#define IMG_R 384
#define IMG_C 384
#define NPIX (IMG_R * IMG_C)
#define PITCH 1024
#define N_COLS 768
#define N_VIEWS 256
#define DSPACE_F 1.5f
#define NSPLIT 8

// padded copies: [384 rows x 1024 pitch], cols 384..1023 are zeros
__device__ float g_row[IMG_R * PITCH];   // g_row[r*1024 + c] = img[r][c]
__device__ float g_col[IMG_C * PITCH];   // g_col[c*1024 + r] = img[r][c]

// tiled transpose + row copy (data region only)
__global__ __launch_bounds__(256) void prep_copy_kernel(const float* __restrict__ in) {
    __shared__ float tile[32][33];
    const int tx = threadIdx.x, ty = threadIdx.y;
    const int bx = blockIdx.x * 32, by = blockIdx.y * 32;
    #pragma unroll
    for (int dy = 0; dy < 32; dy += 8) {
        const float vIn = in[(by + ty + dy) * IMG_C + bx + tx];
        tile[ty + dy][tx] = vIn;
        g_row[(by + ty + dy) * PITCH + bx + tx] = vIn;
    }
    __syncthreads();
    #pragma unroll
    for (int dy = 0; dy < 32; dy += 8)
        g_col[(bx + ty + dy) * PITCH + by + tx] = tile[tx][ty + dy];
}

// zero the pad columns 384..1023 of both arrays
__global__ __launch_bounds__(256) void prep_pad_kernel() {
    const int idx = blockIdx.x * 256 + threadIdx.x;   // 384*640 threads
    const int o = idx / 640;
    const int i = 384 + (idx - o * 640);
    g_row[o * PITCH + i] = 0.0f;
    g_col[o * PITCH + i] = 0.0f;
}

__global__ __launch_bounds__(256)
void fanbeam_gather_kernel(
    const float* __restrict__ src_a,    // (V, 1, 2)
    const float* __restrict__ detc_a,   // (V, 1, 2)
    const float* __restrict__ u_a,      // (V, 1, 2)
    const float* __restrict__ center_a, // (2,)
    const float* __restrict__ cdir_a,   // (2,)
    float* __restrict__ out)            // (V, N_COLS)
{
    const int v     = blockIdx.y;
    const int lane  = threadIdx.x & 31;
    const int split = threadIdx.x >> 5;              // 0..7, strided outer steps
    const int j     = (blockIdx.x << 5) | lane;      // detector column

    // ---- per-view geometry (validated R3/R11) ----
    const float sx  = src_a[2 * v],  sy  = src_a[2 * v + 1];
    const float dcx = detc_a[2 * v], dcy = detc_a[2 * v + 1];
    const float ux  = u_a[2 * v],    uy  = u_a[2 * v + 1];
    const float cx  = center_a[0],   cy  = center_a[1];
    const float cdx = cdir_a[0],     cdy = cdir_a[1];

    const float rdx = -cdy, rdy = cdx;
    const float vzx = cx - 0.5f * (IMG_R - 1) * rdx - 0.5f * (IMG_C - 1) * cdx;
    const float vzy = cy - 0.5f * (IMG_R - 1) * rdy - 0.5f * (IMG_C - 1) * cdy;

    const float nx = -uy, ny = ux;
    const float ref_d = dcx * nx + dcy * ny;
    const float src_d = sx * nx + sy * ny;
    const float nu    = ref_d - src_d;               // t numerator, >0 in this geometry
    const float src_u = sx * ux + sy * uy;
    const float uu    = ux * ux + uy * uy;
    const float zero_u = (dcx * ux + dcy * uy) - 0.5f * (N_COLS - 1) * DSPACE_F * uu;
    const float invD  = 1.0f / DSPACE_F;
    const float su0D  = (src_u - zero_u) * invD;

    const float dn00  = vzx * nx + vzy * ny - src_d;
    const float dnr   = rdx * nx + rdy * ny;
    const float dnc   = cdx * nx + cdy * ny;
    const float pu00D = (vzx * ux + vzy * uy - src_u) * invD;
    const float purD  = (rdx * ux + rdy * uy) * invD;
    const float pucD  = (cdx * ux + cdy * uy) * invD;

    // ---- orientation-adaptive axis swap (block-uniform: depends only on v) ----
    // outer axis = axis the ray crosses the FEWEST steps of (smaller |dn|)
    const bool  trans = fabsf(dnc) < fabsf(dnr);
    const float dn_o = trans ? dnc  : dnr;
    const float dn_i = trans ? dnr  : dnc;
    const float pu_o = trans ? pucD : purD;
    const float pu_i = trans ? purD : pucD;
    const float* __restrict__ base0 = trans ? g_col : g_row;

    // col(o,i)*den(o,i) = A(o) + B*i ; den = dn0(o) + i*dn_i > 0 inside image
    const float A0 = su0D * dn00 + nu * pu00D;
    const float Ao = su0D * dn_o + nu * pu_o;
    const float Bc = su0D * dn_i + nu * pu_i;

    const float jf   = (float)j;
    const float jm   = jf - 1.0f, jp = jf + 1.0f;
    const float sujD = su0D - jf;

    // window constraints as lines in o (inner-coordinate bounds)
    const float bm = Bc - jm * dn_i;
    const float bp = Bc - jp * dn_i;
    const float rBm = __frcp_rn(bm);
    const float rBp = __frcp_rn(bp);
    const float Lm0 = (jm * dn00 - A0) * rBm, Lmo = (jm * dn_o - Ao) * rBm;
    const float Lp0 = (jp * dn00 - A0) * rBp, Lpo = (jp * dn_o - Ao) * rBp;
    const bool m_act = fabsf(bm) > 1e-30f;
    const bool p_act = fabsf(bp) > 1e-30f;

    const bool mlow = m_act && (bm > 0.0f);
    const bool mup  = m_act && (bm < 0.0f);
    const bool plow = p_act && (bp < 0.0f);
    const bool pup  = p_act && (bp > 0.0f);
    float lo1b = mlow ? Lm0 - 0.02f : -1e30f,  lo1s = mlow ? Lmo : 0.0f;
    float hi1b = mup  ? Lm0 + 0.02f :  1e30f,  hi1s = mup  ? Lmo : 0.0f;
    float lo2b = plow ? Lp0 - 0.02f : -1e30f,  lo2s = plow ? Lpo : 0.0f;
    float hi2b = pup  ? Lp0 + 0.02f :  1e30f,  hi2s = pup  ? Lpo : 0.0f;

    // ---- analytic outer range (superset) ----
    const float am0 = A0 - jm * dn00, amo = Ao - jm * dn_o;
    const float ap0 = A0 - jp * dn00, apo = Ao - jp * dn_o;
    const float Km  = fmaxf(0.0f, bm * (float)(IMG_C - 1));
    const float Kp  = fminf(0.0f, bp * (float)(IMG_C - 1));
    float olo_f = 0.0f, ohi_f = (float)(IMG_R - 1);
    bool empty = false;
    {
        const float s = am0 + Km;
        if (amo > 0.0f)       olo_f = fmaxf(olo_f, __fdividef(-s, amo));
        else if (amo < 0.0f)  ohi_f = fminf(ohi_f, __fdividef(-s, amo));
        else if (!(s > 0.0f)) empty = true;
    }
    {
        const float s = ap0 + Kp;
        if (apo < 0.0f)       olo_f = fmaxf(olo_f, __fdividef(-s, apo));
        else if (apo > 0.0f)  ohi_f = fminf(ohi_f, __fdividef(-s, apo));
        else if (!(s < 0.0f)) empty = true;
    }
    int o0 = 0, o1 = -1;
    if (!empty && ohi_f >= olo_f) {
        o0 = max(0, (int)floorf(olo_f) - 1);
        o1 = min(IMG_R - 1, (int)ceilf(ohi_f) + 1);
    }

    // strided outer steps: this thread handles o = o0s, o0s+8, ...
    const int o0s   = o0 + ((split - o0) & (NSPLIT - 1));
    int nrows       = (o1 >= o0s) ? ((o1 - o0s) >> 3) + 1 : 0;
    const int nrows_w = __reduce_max_sync(0xffffffffu, nrows);

    const float os = (float)o0s;
    float lo1 = fmaf(os, lo1s, lo1b), lo2 = fmaf(os, lo2s, lo2b);
    float hi1 = fmaf(os, hi1s, hi1b), hi2 = fmaf(os, hi2s, hi2b);
    const float lo1st = 8.0f * lo1s, lo2st = 8.0f * lo2s;
    const float hi1st = 8.0f * hi1s, hi2st = 8.0f * hi2s;
    float dn0v = fmaf(os, dn_o, dn00);
    float pu0v = fmaf(os, pu_o, pu00D);
    const float dno8 = 8.0f * dn_o, puo8 = 8.0f * pu_o;
    int offo = o0s * PITCH;

    float acc = 0.0f;

    for (int k = 0; k < nrows_w; ++k) {
        const float lo = fmaxf(fmaxf(lo1, lo2), 0.0f);
        const float hi = fminf(fminf(hi1, hi2), (float)(IMG_C - 1));
        const float cf = fminf(ceilf(lo), 400.0f);    // clamp: keeps address in pad
        const bool  pr = (k < nrows);                 // outer index still in this lane's range
        const int   n  = (int)(hi - cf);              // trips-1 (may be <0)
        const int   nw = __reduce_max_sync(0xffffffffu, pr ? n : -1);

        if (nw >= 0) {
            float den = fmaf(cf, dn_i, dn0v);
            float puD = fmaf(cf, pu_i, pu0v);
            puD = pr ? puD : 1e30f;                   // poison: w -> 0 for invalid rows
            const int offbase = pr ? offo : 0;        // keep poisoned addresses in-array
            const float* __restrict__ p = base0 + (offbase + (int)cf);
            // overruns past the true window either have w<=0 (interior) or read
            // pad zeros (image edge) -> contribution exactly 0; no per-iter mask.
            for (int kk = 0; kk <= nw; ++kk) {
                const float t = __fdividef(nu, den);
                float w = 1.0f - fabsf(fmaf(t, puD, sujD));
                w = fmaxf(w, 0.0f);                   // fmaxf(NaN,0)=0 guards poison
                acc = fmaf(w, p[kk], acc);
                den += dn_i; puD += pu_i;
            }
        }
        lo1 += lo1st; lo2 += lo2st; hi1 += hi1st; hi2 += hi2st;
        dn0v += dno8; pu0v += puo8; offo += NSPLIT * PITCH;
    }

    // in-block reduction over the 8 strided splits
    __shared__ float red[NSPLIT][32];
    red[split][lane] = acc;
    __syncthreads();
    if (split == 0) {
        float s = red[0][lane];
        #pragma unroll
        for (int kk = 1; kk < NSPLIT; ++kk)
            s += red[kk][lane];
        out[v * N_COLS + j] = s;
    }
}

extern "C" void kernel_launch(void* const* d_in, const int* in_sizes, int n_in,
                              void* d_out, int out_size) {
    const float* img    = (const float*)d_in[0];
    const float* src    = (const float*)d_in[1];
    const float* detc   = (const float*)d_in[2];
    const float* u      = (const float*)d_in[3];
    const float* center = (const float*)d_in[4];
    const float* cdir   = (const float*)d_in[5];
    float* out = (float*)d_out;

    dim3 tgrid(IMG_C / 32, IMG_R / 32);
    prep_copy_kernel<<<tgrid, dim3(32, 8)>>>(img);
    prep_pad_kernel<<<(IMG_R * (PITCH - IMG_C)) / 256, 256>>>();

    dim3 grid(N_COLS / 32, N_VIEWS);
    fanbeam_gather_kernel<<<grid, 256>>>(src, detc, u, center, cdir, out);
}